// round 1
// baseline (speedup 1.0000x reference)
#include <cuda_runtime.h>
#include <math.h>

// Problem constants
#define KB 4
#define KN 4096
#define KM 4096
#define KC 256
#define KROWS (KB * KN)   // 16384 rows for both L and R sides

// -------------------- device scratch (allocation-free) ---------------------
__device__ float g_Q[KB * KN * KC];
__device__ float g_K[KB * KM * KC];
__device__ float g_V[KB * KM * KC];
__device__ float g_MF[KB * KN * KC];   // matched features before out-projection

// ---------------------------------------------------------------------------
// SGEMM (NT with bias):  C[r,o] = sum_k A[r,k] * W[o,k] + bias[o]
// A: [R, 256] row-major, W: [256, 256] row-major (torch Linear weight layout).
// Tile 64x64, BK=16, 256 threads, 4x4 outputs/thread. R and 256 are multiples
// of 64 so no bounds checks.
// ---------------------------------------------------------------------------
__global__ void sgemm_nt_bias(const float* __restrict__ A,
                              const float* __restrict__ W,
                              const float* __restrict__ bias,
                              float* __restrict__ Cout)
{
    __shared__ float As[64][17];
    __shared__ float Ws[64][17];

    const int block_row = blockIdx.y * 64;
    const int block_col = blockIdx.x * 64;
    const int tid  = threadIdx.x;      // 0..255
    const int tx   = tid & 15;
    const int ty   = tid >> 4;
    const int lrow = tid >> 2;         // 0..63
    const int lcol = (tid & 3) * 4;    // 0,4,8,12

    float acc[4][4];
#pragma unroll
    for (int i = 0; i < 4; i++)
#pragma unroll
        for (int j = 0; j < 4; j++) acc[i][j] = 0.0f;

    for (int k0 = 0; k0 < KC; k0 += 16) {
        float4 a4 = *reinterpret_cast<const float4*>(
            A + (size_t)(block_row + lrow) * KC + k0 + lcol);
        float4 w4 = *reinterpret_cast<const float4*>(
            W + (size_t)(block_col + lrow) * KC + k0 + lcol);
        As[lrow][lcol + 0] = a4.x; As[lrow][lcol + 1] = a4.y;
        As[lrow][lcol + 2] = a4.z; As[lrow][lcol + 3] = a4.w;
        Ws[lrow][lcol + 0] = w4.x; Ws[lrow][lcol + 1] = w4.y;
        Ws[lrow][lcol + 2] = w4.z; Ws[lrow][lcol + 3] = w4.w;
        __syncthreads();

#pragma unroll
        for (int kk = 0; kk < 16; kk++) {
            float ar[4], wr[4];
#pragma unroll
            for (int i = 0; i < 4; i++) ar[i] = As[ty * 4 + i][kk];
#pragma unroll
            for (int j = 0; j < 4; j++) wr[j] = Ws[tx * 4 + j][kk];
#pragma unroll
            for (int i = 0; i < 4; i++)
#pragma unroll
                for (int j = 0; j < 4; j++)
                    acc[i][j] = fmaf(ar[i], wr[j], acc[i][j]);
        }
        __syncthreads();
    }

#pragma unroll
    for (int i = 0; i < 4; i++) {
        const int r = block_row + ty * 4 + i;
#pragma unroll
        for (int j = 0; j < 4; j++) {
            const int o = block_col + tx * 4 + j;
            Cout[(size_t)r * KC + o] = acc[i][j] + bias[o];
        }
    }
}

// ---------------------------------------------------------------------------
// Sparse epipolar attention. One block (256 threads) per (b, n) query row.
// The mask admits ~10 of 4096 keys per row; masked logits are -1e9 in the
// reference, whose exp() underflows to exactly 0.0f, so computing softmax
// over only the valid set is EXACT. Fully-masked rows reproduce the exact
// uniform 1/M softmax of the reference.
// ---------------------------------------------------------------------------
__global__ void attn_sparse_kernel(const float* __restrict__ kptsL,
                                   const float* __restrict__ kptsR,
                                   float* __restrict__ attn,
                                   float* __restrict__ disp,
                                   float* __restrict__ conf)
{
    extern __shared__ char smem_raw[];
    int*   s_idx = reinterpret_cast<int*>(smem_raw);        // [KM]
    float* s_du  = reinterpret_cast<float*>(s_idx + KM);    // [KM]
    float* s_sc  = s_du + KM;                               // [KM]
    float* s_q   = s_sc + KM;                               // [KC]
    float* s_red = s_q + KC;                                // [256]
    __shared__ int s_cnt;

    const int row = blockIdx.x;           // 0..B*N-1
    const int b   = row >> 12;            // row / 4096
    const int tid = threadIdx.x;

    if (tid == 0) s_cnt = 0;
    __syncthreads();

    const float uL = kptsL[(size_t)row * 2 + 0];
    const float vL = kptsL[(size_t)row * 2 + 1];
    const float* kR = kptsR + (size_t)b * KM * 2;

    // Phase A: compact list of valid keys
    for (int m = tid; m < KM; m += 256) {
        const float uR = kR[2 * m];
        const float vR = kR[2 * m + 1];
        const float du = uL - uR;
        if (fabsf(vL - vR) < 3.0f && du > 0.0f && du < 192.0f) {
            const int p = atomicAdd(&s_cnt, 1);
            s_idx[p] = m;
            s_du[p]  = du;
        }
    }
    s_q[tid] = g_Q[(size_t)row * KC + tid];
    __syncthreads();

    const int cnt = s_cnt;
    float* attn_row = attn + (size_t)row * KM;

    if (cnt > 0) {
        // Phase B: scores, one warp per valid entry
        const int wid = tid >> 5, lane = tid & 31;
        const float* Kb = g_K + (size_t)b * KM * KC;
        for (int i = wid; i < cnt; i += 8) {
            const float* krow = Kb + (size_t)s_idx[i] * KC;
            float sum = 0.0f;
#pragma unroll
            for (int c = lane; c < KC; c += 32) sum += s_q[c] * __ldg(krow + c);
#pragma unroll
            for (int o = 16; o > 0; o >>= 1)
                sum += __shfl_xor_sync(0xffffffffu, sum, o);
            if (lane == 0) s_sc[i] = sum * 0.0625f;   // 1/sqrt(256)
        }
        __syncthreads();

        // max
        float mx = -1e30f;
        for (int i = tid; i < cnt; i += 256) mx = fmaxf(mx, s_sc[i]);
        s_red[tid] = mx; __syncthreads();
        for (int s = 128; s > 0; s >>= 1) {
            if (tid < s) s_red[tid] = fmaxf(s_red[tid], s_red[tid + s]);
            __syncthreads();
        }
        mx = s_red[0];
        __syncthreads();

        // sum of exp
        float sm = 0.0f;
        for (int i = tid; i < cnt; i += 256) {
            const float e = expf(s_sc[i] - mx);
            s_sc[i] = e;
            sm += e;
        }
        s_red[tid] = sm; __syncthreads();
        for (int s = 128; s > 0; s >>= 1) {
            if (tid < s) s_red[tid] += s_red[tid + s];
            __syncthreads();
        }
        const float inv = 1.0f / s_red[0];
        __syncthreads();

        // weights + disparity
        float dsum = 0.0f;
        for (int i = tid; i < cnt; i += 256) {
            const float w = s_sc[i] * inv;
            s_sc[i] = w;
            dsum += w * s_du[i];
        }
        s_red[tid] = dsum; __syncthreads();
        for (int s = 128; s > 0; s >>= 1) {
            if (tid < s) s_red[tid] += s_red[tid + s];
            __syncthreads();
        }

        // attn row: zeros + scatter of weights (exact vs reference underflow)
        for (int m = tid; m < KM; m += 256) attn_row[m] = 0.0f;
        __syncthreads();
        for (int i = tid; i < cnt; i += 256) attn_row[s_idx[i]] = s_sc[i];

        // matched features: each thread owns one channel
        const float* Vb = g_V + (size_t)b * KM * KC;
        float a = 0.0f;
        for (int i = 0; i < cnt; i++)
            a = fmaf(s_sc[i], __ldg(Vb + (size_t)s_idx[i] * KC + tid), a);
        g_MF[(size_t)row * KC + tid] = a;

        if (tid == 0) { disp[row] = s_red[0]; conf[row] = 1.0f; }
    } else {
        // Fully-masked row: softmax of all -1e9 is exactly uniform 1/M
        const float wu = 1.0f / (float)KM;
        for (int m = tid; m < KM; m += 256) attn_row[m] = wu;

        const float* Vb = g_V + (size_t)b * KM * KC;
        float a = 0.0f;
        for (int m = 0; m < KM; m++) a += Vb[(size_t)m * KC + tid];
        g_MF[(size_t)row * KC + tid] = a * wu;

        float su = 0.0f;
        for (int m = tid; m < KM; m += 256) su += kR[2 * m];
        s_red[tid] = su; __syncthreads();
        for (int s = 128; s > 0; s >>= 1) {
            if (tid < s) s_red[tid] += s_red[tid + s];
            __syncthreads();
        }
        if (tid == 0) { disp[row] = uL - s_red[0] * wu; conf[row] = 0.0f; }
    }
}

// ---------------------------------------------------------------------------
extern "C" void kernel_launch(void* const* d_in, const int* in_sizes, int n_in,
                              void* d_out, int out_size)
{
    (void)in_sizes; (void)n_in; (void)out_size;

    const float* nodes_L = (const float*)d_in[0];
    const float* nodes_R = (const float*)d_in[1];
    const float* kpts_L  = (const float*)d_in[2];
    const float* kpts_R  = (const float*)d_in[3];
    const float* Wq = (const float*)d_in[4];
    const float* bq = (const float*)d_in[5];
    const float* Wk = (const float*)d_in[6];
    const float* bk = (const float*)d_in[7];
    const float* Wv = (const float*)d_in[8];
    const float* bv = (const float*)d_in[9];
    const float* Wm = (const float*)d_in[10];
    const float* bm = (const float*)d_in[11];

    // Output tuple layout: out [B,N,C], disparity [B,N,1], confidence [B,N,1],
    // attn_weights [B,N,M] -- concatenated flat.
    float* out      = (float*)d_out;
    float* out_feat = out;
    float* out_disp = out_feat + (size_t)KB * KN * KC;
    float* out_conf = out_disp + (size_t)KB * KN;
    float* out_attn = out_conf + (size_t)KB * KN;

    float *pQ, *pK, *pV, *pMF;
    cudaGetSymbolAddress((void**)&pQ,  g_Q);
    cudaGetSymbolAddress((void**)&pK,  g_K);
    cudaGetSymbolAddress((void**)&pV,  g_V);
    cudaGetSymbolAddress((void**)&pMF, g_MF);

    const dim3 ggrid(KC / 64, KROWS / 64);   // (4, 256)

    // Q/K/V projections
    sgemm_nt_bias<<<ggrid, 256>>>(nodes_L, Wq, bq, pQ);
    sgemm_nt_bias<<<ggrid, 256>>>(nodes_R, Wk, bk, pK);
    sgemm_nt_bias<<<ggrid, 256>>>(nodes_R, Wv, bv, pV);

    // Sparse masked attention (needs >48KB dynamic smem)
    const size_t smem = (size_t)KM * sizeof(int)        // s_idx
                      + (size_t)KM * sizeof(float) * 2  // s_du, s_sc
                      + (size_t)KC * sizeof(float)      // s_q
                      + 256 * sizeof(float);            // s_red
    cudaFuncSetAttribute(attn_sparse_kernel,
                         cudaFuncAttributeMaxDynamicSharedMemorySize, (int)smem);
    attn_sparse_kernel<<<KB * KN, 256, smem>>>(kpts_L, kpts_R,
                                               out_attn, out_disp, out_conf);

    // Output projection
    sgemm_nt_bias<<<ggrid, 256>>>(pMF, Wm, bm, out_feat);
}

// round 2
// speedup vs baseline: 1.2172x; 1.2172x over previous
#include <cuda_runtime.h>
#include <math.h>

// Problem constants
#define KB 4
#define KN 4096
#define KM 4096
#define KC 256
#define KROWS (KB * KN)
#define NBINS 376
#define CAP 2048          // max compacted valid keys per query row (≈10 expected)

// -------------------- device scratch (allocation-free) ---------------------
__device__ float  g_Q[KB * KN * KC];
__device__ float  g_K[KB * KM * KC];
__device__ float  g_V[KB * KM * KC];
__device__ float  g_MF[KB * KN * KC];
__device__ float2 g_bin_uv[KB * KM];
__device__ int    g_bin_idx[KB * KM];
__device__ int    g_bin_off[KB * (NBINS + 1)];

// ---------------------------------------------------------------------------
// Bucket kpts_R rows of one batch by floor(v) into a CSR structure.
// One block per batch.
// ---------------------------------------------------------------------------
__global__ void build_bins_kernel(const float* __restrict__ kptsR)
{
    const int b   = blockIdx.x;
    const int tid = threadIdx.x;
    __shared__ int cnt[NBINS];
    __shared__ int off[NBINS + 1];
    __shared__ int cur[NBINS];

    for (int i = tid; i < NBINS; i += blockDim.x) cnt[i] = 0;
    __syncthreads();

    const float* kR = kptsR + (size_t)b * KM * 2;
    for (int m = tid; m < KM; m += blockDim.x) {
        int bin = (int)kR[2 * m + 1];
        bin = max(0, min(NBINS - 1, bin));
        atomicAdd(&cnt[bin], 1);
    }
    __syncthreads();

    if (tid == 0) {
        off[0] = 0;
        for (int i = 0; i < NBINS; i++) off[i + 1] = off[i] + cnt[i];
    }
    __syncthreads();

    for (int i = tid; i < NBINS; i += blockDim.x) cur[i] = off[i];
    __syncthreads();

    for (int m = tid; m < KM; m += blockDim.x) {
        const float u = kR[2 * m];
        const float v = kR[2 * m + 1];
        int bin = max(0, min(NBINS - 1, (int)v));
        const int p = atomicAdd(&cur[bin], 1);
        g_bin_uv[(size_t)b * KM + p]  = make_float2(u, v);
        g_bin_idx[(size_t)b * KM + p] = m;
    }

    for (int i = tid; i <= NBINS; i += blockDim.x)
        g_bin_off[b * (NBINS + 1) + i] = off[i];
}

// ---------------------------------------------------------------------------
// SGEMM (NT with bias): C[r,o] = sum_k A[r,k]*W[o,k] + bias[o]
// 128x128 tile, BK=8, 256 threads, 8x8 outputs/thread.
// ---------------------------------------------------------------------------
__device__ __forceinline__ void sgemm_body(const float* __restrict__ A,
                                           const float* __restrict__ W,
                                           const float* __restrict__ bias,
                                           float* __restrict__ Cout)
{
    __shared__ float As[8][128];
    __shared__ float Bs[8][128];

    const int row0 = blockIdx.y * 128;
    const int col0 = blockIdx.x * 128;
    const int tid  = threadIdx.x;
    const int tx   = tid & 15;          // 0..15
    const int ty   = tid >> 4;          // 0..15
    const int l_m  = tid >> 1;          // 0..127
    const int l_k  = (tid & 1) * 4;     // 0 or 4

    const float* Aptr = A + (size_t)(row0 + l_m) * KC + l_k;
    const float* Wptr = W + (size_t)(col0 + l_m) * KC + l_k;

    float acc[8][8];
#pragma unroll
    for (int i = 0; i < 8; i++)
#pragma unroll
        for (int j = 0; j < 8; j++) acc[i][j] = 0.0f;

    for (int k0 = 0; k0 < KC; k0 += 8) {
        float4 a4 = *reinterpret_cast<const float4*>(Aptr + k0);
        float4 w4 = *reinterpret_cast<const float4*>(Wptr + k0);
        As[l_k + 0][l_m] = a4.x; As[l_k + 1][l_m] = a4.y;
        As[l_k + 2][l_m] = a4.z; As[l_k + 3][l_m] = a4.w;
        Bs[l_k + 0][l_m] = w4.x; Bs[l_k + 1][l_m] = w4.y;
        Bs[l_k + 2][l_m] = w4.z; Bs[l_k + 3][l_m] = w4.w;
        __syncthreads();

#pragma unroll
        for (int kk = 0; kk < 8; kk++) {
            float4 a0 = *reinterpret_cast<const float4*>(&As[kk][ty * 8]);
            float4 a1 = *reinterpret_cast<const float4*>(&As[kk][ty * 8 + 4]);
            float4 b0 = *reinterpret_cast<const float4*>(&Bs[kk][tx * 8]);
            float4 b1 = *reinterpret_cast<const float4*>(&Bs[kk][tx * 8 + 4]);
            float ar[8] = {a0.x, a0.y, a0.z, a0.w, a1.x, a1.y, a1.z, a1.w};
            float br[8] = {b0.x, b0.y, b0.z, b0.w, b1.x, b1.y, b1.z, b1.w};
#pragma unroll
            for (int i = 0; i < 8; i++)
#pragma unroll
                for (int j = 0; j < 8; j++)
                    acc[i][j] = fmaf(ar[i], br[j], acc[i][j]);
        }
        __syncthreads();
    }

    const float4 bias0 = *reinterpret_cast<const float4*>(bias + col0 + tx * 8);
    const float4 bias1 = *reinterpret_cast<const float4*>(bias + col0 + tx * 8 + 4);
#pragma unroll
    for (int i = 0; i < 8; i++) {
        const size_t r = (size_t)(row0 + ty * 8 + i);
        float4 c0, c1;
        c0.x = acc[i][0] + bias0.x; c0.y = acc[i][1] + bias0.y;
        c0.z = acc[i][2] + bias0.z; c0.w = acc[i][3] + bias0.w;
        c1.x = acc[i][4] + bias1.x; c1.y = acc[i][5] + bias1.y;
        c1.z = acc[i][6] + bias1.z; c1.w = acc[i][7] + bias1.w;
        *reinterpret_cast<float4*>(Cout + r * KC + col0 + tx * 8)     = c0;
        *reinterpret_cast<float4*>(Cout + r * KC + col0 + tx * 8 + 4) = c1;
    }
}

// Fused QKV projection: blockIdx.z selects {Q, K, V}.
__global__ void __launch_bounds__(256, 2)
sgemm_qkv(const float* __restrict__ nodes_L, const float* __restrict__ nodes_R,
          const float* __restrict__ Wq, const float* __restrict__ bq,
          const float* __restrict__ Wk, const float* __restrict__ bk,
          const float* __restrict__ Wv, const float* __restrict__ bv,
          float* __restrict__ Q, float* __restrict__ K, float* __restrict__ V)
{
    const int z = blockIdx.z;
    const float* A    = (z == 0) ? nodes_L : nodes_R;
    const float* W    = (z == 0) ? Wq : (z == 1) ? Wk : Wv;
    const float* bias = (z == 0) ? bq : (z == 1) ? bk : bv;
    float*       C    = (z == 0) ? Q  : (z == 1) ? K  : V;
    sgemm_body(A, W, bias, C);
}

__global__ void __launch_bounds__(256, 2)
sgemm_out(const float* __restrict__ A, const float* __restrict__ W,
          const float* __restrict__ bias, float* __restrict__ C)
{
    sgemm_body(A, W, bias, C);
}

// ---------------------------------------------------------------------------
// Sparse epipolar attention, one block per query row, using the v-bin CSR to
// restrict candidates to a contiguous segment (~77 of 4096 keys).
// ---------------------------------------------------------------------------
__global__ void attn_sparse_kernel(const float* __restrict__ kptsL,
                                   const float* __restrict__ kptsR,
                                   float* __restrict__ attn,
                                   float* __restrict__ disp,
                                   float* __restrict__ conf)
{
    __shared__ int   s_idx[CAP];
    __shared__ float s_du[CAP];
    __shared__ float s_sc[CAP];
    __shared__ float s_q[KC];
    __shared__ float s_red[256];
    __shared__ int   s_cnt;

    const int row = blockIdx.x;
    const int b   = row >> 12;
    const int tid = threadIdx.x;

    if (tid == 0) s_cnt = 0;
    __syncthreads();

    const float uL = kptsL[(size_t)row * 2 + 0];
    const float vL = kptsL[(size_t)row * 2 + 1];

    // candidate segment from v-bins
    int lo = (int)floorf(vL - 3.0f); lo = max(lo, 0);
    int hi = (int)floorf(vL + 3.0f); hi = min(hi, NBINS - 1);
    const int* off   = g_bin_off + b * (NBINS + 1);
    const int  start = off[lo];
    const int  end   = off[hi + 1];

    for (int j = start + tid; j < end; j += 256) {
        const float2 uv = g_bin_uv[(size_t)b * KM + j];
        const float du = uL - uv.x;
        if (fabsf(vL - uv.y) < 3.0f && du > 0.0f && du < 192.0f) {
            const int p = atomicAdd(&s_cnt, 1);
            if (p < CAP) {
                s_idx[p] = g_bin_idx[(size_t)b * KM + j];
                s_du[p]  = du;
            }
        }
    }
    s_q[tid] = g_Q[(size_t)row * KC + tid];
    __syncthreads();

    const int cnt = min(s_cnt, CAP);
    float* attn_row = attn + (size_t)row * KM;

    if (cnt > 0) {
        // scores: one warp per valid entry
        const int wid = tid >> 5, lane = tid & 31;
        const float* Kb = g_K + (size_t)b * KM * KC;
        for (int i = wid; i < cnt; i += 8) {
            const float* krow = Kb + (size_t)s_idx[i] * KC;
            float sum = 0.0f;
#pragma unroll
            for (int c = lane; c < KC; c += 32) sum += s_q[c] * __ldg(krow + c);
#pragma unroll
            for (int o = 16; o > 0; o >>= 1)
                sum += __shfl_xor_sync(0xffffffffu, sum, o);
            if (lane == 0) s_sc[i] = sum * 0.0625f;   // 1/sqrt(256)
        }
        __syncthreads();

        // max
        float mx = -1e30f;
        for (int i = tid; i < cnt; i += 256) mx = fmaxf(mx, s_sc[i]);
        s_red[tid] = mx; __syncthreads();
        for (int s = 128; s > 0; s >>= 1) {
            if (tid < s) s_red[tid] = fmaxf(s_red[tid], s_red[tid + s]);
            __syncthreads();
        }
        mx = s_red[0];
        __syncthreads();

        // sum exp
        float sm = 0.0f;
        for (int i = tid; i < cnt; i += 256) {
            const float e = expf(s_sc[i] - mx);
            s_sc[i] = e;
            sm += e;
        }
        s_red[tid] = sm; __syncthreads();
        for (int s = 128; s > 0; s >>= 1) {
            if (tid < s) s_red[tid] += s_red[tid + s];
            __syncthreads();
        }
        const float inv = 1.0f / s_red[0];
        __syncthreads();

        // weights + disparity
        float dsum = 0.0f;
        for (int i = tid; i < cnt; i += 256) {
            const float w = s_sc[i] * inv;
            s_sc[i] = w;
            dsum += w * s_du[i];
        }
        s_red[tid] = dsum; __syncthreads();
        for (int s = 128; s > 0; s >>= 1) {
            if (tid < s) s_red[tid] += s_red[tid + s];
            __syncthreads();
        }

        // attn row: zero-fill + scatter (exact: masked exps underflow to 0)
        for (int m = tid; m < KM; m += 256) attn_row[m] = 0.0f;
        __syncthreads();
        for (int i = tid; i < cnt; i += 256) attn_row[s_idx[i]] = s_sc[i];

        // matched features: each thread owns one channel
        const float* Vb = g_V + (size_t)b * KM * KC;
        float a = 0.0f;
        for (int i = 0; i < cnt; i++)
            a = fmaf(s_sc[i], __ldg(Vb + (size_t)s_idx[i] * KC + tid), a);
        g_MF[(size_t)row * KC + tid] = a;

        if (tid == 0) { disp[row] = s_red[0]; conf[row] = 1.0f; }
    } else {
        // fully-masked row: softmax of all -1e9 == uniform 1/M (exact)
        const float wu = 1.0f / (float)KM;
        for (int m = tid; m < KM; m += 256) attn_row[m] = wu;

        const float* Vb = g_V + (size_t)b * KM * KC;
        float a = 0.0f;
        for (int m = 0; m < KM; m++) a += Vb[(size_t)m * KC + tid];
        g_MF[(size_t)row * KC + tid] = a * wu;

        const float* kR = kptsR + (size_t)b * KM * 2;
        float su = 0.0f;
        for (int m = tid; m < KM; m += 256) su += kR[2 * m];
        s_red[tid] = su; __syncthreads();
        for (int s = 128; s > 0; s >>= 1) {
            if (tid < s) s_red[tid] += s_red[tid + s];
            __syncthreads();
        }
        if (tid == 0) { disp[row] = uL - s_red[0] * wu; conf[row] = 0.0f; }
    }
}

// ---------------------------------------------------------------------------
extern "C" void kernel_launch(void* const* d_in, const int* in_sizes, int n_in,
                              void* d_out, int out_size)
{
    (void)in_sizes; (void)n_in; (void)out_size;

    const float* nodes_L = (const float*)d_in[0];
    const float* nodes_R = (const float*)d_in[1];
    const float* kpts_L  = (const float*)d_in[2];
    const float* kpts_R  = (const float*)d_in[3];
    const float* Wq = (const float*)d_in[4];
    const float* bq = (const float*)d_in[5];
    const float* Wk = (const float*)d_in[6];
    const float* bk = (const float*)d_in[7];
    const float* Wv = (const float*)d_in[8];
    const float* bv = (const float*)d_in[9];
    const float* Wm = (const float*)d_in[10];
    const float* bm = (const float*)d_in[11];

    float* out      = (float*)d_out;
    float* out_feat = out;
    float* out_disp = out_feat + (size_t)KB * KN * KC;
    float* out_conf = out_disp + (size_t)KB * KN;
    float* out_attn = out_conf + (size_t)KB * KN;

    float *pQ, *pK, *pV, *pMF;
    cudaGetSymbolAddress((void**)&pQ,  g_Q);
    cudaGetSymbolAddress((void**)&pK,  g_K);
    cudaGetSymbolAddress((void**)&pV,  g_V);
    cudaGetSymbolAddress((void**)&pMF, g_MF);

    // v-bin CSR for kpts_R (tiny)
    build_bins_kernel<<<KB, 512>>>(kpts_R);

    // fused Q/K/V projections: 128x128 tiles, grid.z selects the GEMM
    dim3 qkv_grid(KC / 128, KROWS / 128, 3);   // (2, 128, 3)
    sgemm_qkv<<<qkv_grid, 256>>>(nodes_L, nodes_R, Wq, bq, Wk, bk, Wv, bv,
                                 pQ, pK, pV);

    // sparse masked attention
    attn_sparse_kernel<<<KB * KN, 256>>>(kpts_L, kpts_R,
                                         out_attn, out_disp, out_conf);

    // output projection
    dim3 out_grid(KC / 128, KROWS / 128);
    sgemm_out<<<out_grid, 256>>>(pMF, Wm, bm, out_feat);
}

// round 3
// speedup vs baseline: 1.7338x; 1.4244x over previous
#include <cuda_runtime.h>
#include <math.h>

// Problem constants
#define KB 4
#define KN 4096
#define KM 4096
#define KC 256
#define KROWS (KB * KN)
#define NBINS 376
#define CAP 2048

// -------------------- device scratch (allocation-free) ---------------------
__device__ float  g_Q[KB * KN * KC];
__device__ float  g_K[KB * KM * KC];
__device__ float  g_V[KB * KM * KC];
__device__ float  g_MF[KB * KN * KC];
__device__ float2 g_bin_uv[KB * KM];
__device__ int    g_bin_idx[KB * KM];
__device__ int    g_bin_off[KB * (NBINS + 1)];

// ---------------------------------------------------------------------------
// v-bin CSR for kpts_R, one block per batch
// ---------------------------------------------------------------------------
__global__ void build_bins_kernel(const float* __restrict__ kptsR)
{
    const int b   = blockIdx.x;
    const int tid = threadIdx.x;
    __shared__ int cnt[NBINS];
    __shared__ int off[NBINS + 1];
    __shared__ int cur[NBINS];

    for (int i = tid; i < NBINS; i += blockDim.x) cnt[i] = 0;
    __syncthreads();

    const float* kR = kptsR + (size_t)b * KM * 2;
    for (int m = tid; m < KM; m += blockDim.x) {
        int bin = (int)kR[2 * m + 1];
        bin = max(0, min(NBINS - 1, bin));
        atomicAdd(&cnt[bin], 1);
    }
    __syncthreads();

    if (tid == 0) {
        off[0] = 0;
        for (int i = 0; i < NBINS; i++) off[i + 1] = off[i] + cnt[i];
    }
    __syncthreads();

    for (int i = tid; i < NBINS; i += blockDim.x) cur[i] = off[i];
    __syncthreads();

    for (int m = tid; m < KM; m += blockDim.x) {
        const float u = kR[2 * m];
        const float v = kR[2 * m + 1];
        int bin = max(0, min(NBINS - 1, (int)v));
        const int p = atomicAdd(&cur[bin], 1);
        g_bin_uv[(size_t)b * KM + p]  = make_float2(u, v);
        g_bin_idx[(size_t)b * KM + p] = m;
    }

    for (int i = tid; i <= NBINS; i += blockDim.x)
        g_bin_off[b * (NBINS + 1) + i] = off[i];
}

// ---------------------------------------------------------------------------
// tf32 tensor-core GEMM (NT with bias): C[r,o] = sum_k A[r,k]*W[o,k] + b[o]
// 128x128x32 block tile, 8 warps (2m x 4n), warp tile 64x32,
// mma.sync.aligned.m16n8k8.row.col.f32.tf32.tf32.f32, fp32 accumulate.
// ---------------------------------------------------------------------------
#define BM 128
#define BN 128
#define BBK 32
#define SPAD 4

__device__ __forceinline__ unsigned f2tf32(float x)
{
    unsigned u;
    asm("cvt.rna.tf32.f32 %0, %1;" : "=r"(u) : "f"(x));
    return u;
}

__device__ __forceinline__ void gemm_tf32_body(const float* __restrict__ A,
                                               const float* __restrict__ W,
                                               const float* __restrict__ bias,
                                               float* __restrict__ Cout)
{
    __shared__ unsigned As[BBK][BM + SPAD];   // [k][m]
    __shared__ unsigned Bs[BBK][BN + SPAD];   // [k][n]  (n = output channel)

    const int row0 = blockIdx.y * BM;
    const int col0 = blockIdx.x * BN;
    const int tid  = threadIdx.x;
    const int warp = tid >> 5;
    const int lane = tid & 31;
    const int grp  = lane >> 2;      // 0..7
    const int tg   = lane & 3;       // 0..3
    const int wm   = (warp & 1) * 64;
    const int wn   = (warp >> 1) * 32;

    float acc[4][4][4];
#pragma unroll
    for (int mt = 0; mt < 4; mt++)
#pragma unroll
        for (int nt = 0; nt < 4; nt++)
#pragma unroll
            for (int e = 0; e < 4; e++) acc[mt][nt][e] = 0.0f;

#pragma unroll 1
    for (int k0 = 0; k0 < KC; k0 += BBK) {
        // cooperative load: 128 rows x 32 k, 4 float4 per thread per matrix
#pragma unroll
        for (int j = 0; j < 4; j++) {
            const int idx = tid + j * 256;
            const int r   = idx >> 3;           // 0..127
            const int kq  = (idx & 7) * 4;      // 0,4,..28
            float4 a4 = *reinterpret_cast<const float4*>(
                A + (size_t)(row0 + r) * KC + k0 + kq);
            As[kq + 0][r] = f2tf32(a4.x);
            As[kq + 1][r] = f2tf32(a4.y);
            As[kq + 2][r] = f2tf32(a4.z);
            As[kq + 3][r] = f2tf32(a4.w);
            float4 w4 = *reinterpret_cast<const float4*>(
                W + (size_t)(col0 + r) * KC + k0 + kq);
            Bs[kq + 0][r] = f2tf32(w4.x);
            Bs[kq + 1][r] = f2tf32(w4.y);
            Bs[kq + 2][r] = f2tf32(w4.z);
            Bs[kq + 3][r] = f2tf32(w4.w);
        }
        __syncthreads();

#pragma unroll
        for (int ks = 0; ks < BBK; ks += 8) {
            unsigned a[4][4], b[4][2];
#pragma unroll
            for (int mt = 0; mt < 4; mt++) {
                const int m = wm + mt * 16 + grp;
                a[mt][0] = As[ks + tg][m];
                a[mt][1] = As[ks + tg][m + 8];
                a[mt][2] = As[ks + tg + 4][m];
                a[mt][3] = As[ks + tg + 4][m + 8];
            }
#pragma unroll
            for (int nt = 0; nt < 4; nt++) {
                const int n = wn + nt * 8 + grp;
                b[nt][0] = Bs[ks + tg][n];
                b[nt][1] = Bs[ks + tg + 4][n];
            }
#pragma unroll
            for (int mt = 0; mt < 4; mt++)
#pragma unroll
                for (int nt = 0; nt < 4; nt++)
                    asm volatile(
                        "mma.sync.aligned.m16n8k8.row.col.f32.tf32.tf32.f32 "
                        "{%0,%1,%2,%3}, {%4,%5,%6,%7}, {%8,%9}, {%0,%1,%2,%3};"
                        : "+f"(acc[mt][nt][0]), "+f"(acc[mt][nt][1]),
                          "+f"(acc[mt][nt][2]), "+f"(acc[mt][nt][3])
                        : "r"(a[mt][0]), "r"(a[mt][1]),
                          "r"(a[mt][2]), "r"(a[mt][3]),
                          "r"(b[nt][0]), "r"(b[nt][1]));
        }
        __syncthreads();
    }

    // epilogue: c0/c1 at (m, n+2tg..+1), c2/c3 at (m+8, ..)
#pragma unroll
    for (int mt = 0; mt < 4; mt++) {
        const int m = row0 + wm + mt * 16 + grp;
#pragma unroll
        for (int nt = 0; nt < 4; nt++) {
            const int n = col0 + wn + nt * 8 + 2 * tg;
            const float2 bv = *reinterpret_cast<const float2*>(bias + n);
            float2 o0, o1;
            o0.x = acc[mt][nt][0] + bv.x;
            o0.y = acc[mt][nt][1] + bv.y;
            o1.x = acc[mt][nt][2] + bv.x;
            o1.y = acc[mt][nt][3] + bv.y;
            *reinterpret_cast<float2*>(Cout + (size_t)m * KC + n)       = o0;
            *reinterpret_cast<float2*>(Cout + (size_t)(m + 8) * KC + n) = o1;
        }
    }
}

__global__ void __launch_bounds__(256, 2)
gemm_qkv(const float* __restrict__ nodes_L, const float* __restrict__ nodes_R,
         const float* __restrict__ Wq, const float* __restrict__ bq,
         const float* __restrict__ Wk, const float* __restrict__ bk,
         const float* __restrict__ Wv, const float* __restrict__ bv,
         float* __restrict__ Q, float* __restrict__ K, float* __restrict__ V)
{
    const int z = blockIdx.z;
    const float* A    = (z == 0) ? nodes_L : nodes_R;
    const float* W    = (z == 0) ? Wq : (z == 1) ? Wk : Wv;
    const float* bias = (z == 0) ? bq : (z == 1) ? bk : bv;
    float*       C    = (z == 0) ? Q  : (z == 1) ? K  : V;
    gemm_tf32_body(A, W, bias, C);
}

__global__ void __launch_bounds__(256, 2)
gemm_out(const float* __restrict__ A, const float* __restrict__ W,
         const float* __restrict__ bias, float* __restrict__ C)
{
    gemm_tf32_body(A, W, bias, C);
}

// ---------------------------------------------------------------------------
// Sparse epipolar attention, one block per query row, v-bin CSR candidates.
// ---------------------------------------------------------------------------
__global__ void attn_sparse_kernel(const float* __restrict__ kptsL,
                                   const float* __restrict__ kptsR,
                                   float* __restrict__ attn,
                                   float* __restrict__ disp,
                                   float* __restrict__ conf)
{
    __shared__ int   s_idx[CAP];
    __shared__ float s_du[CAP];
    __shared__ float s_sc[CAP];
    __shared__ __align__(16) float s_q[KC];
    __shared__ float s_red[256];
    __shared__ int   s_cnt;

    const int row = blockIdx.x;
    const int b   = row >> 12;
    const int tid = threadIdx.x;

    if (tid == 0) s_cnt = 0;
    __syncthreads();

    const float uL = kptsL[(size_t)row * 2 + 0];
    const float vL = kptsL[(size_t)row * 2 + 1];

    int lo = (int)floorf(vL - 3.0f); lo = max(lo, 0);
    int hi = (int)floorf(vL + 3.0f); hi = min(hi, NBINS - 1);
    const int* off   = g_bin_off + b * (NBINS + 1);
    const int  start = off[lo];
    const int  end   = off[hi + 1];

    for (int j = start + tid; j < end; j += 256) {
        const float2 uv = g_bin_uv[(size_t)b * KM + j];
        const float du = uL - uv.x;
        if (fabsf(vL - uv.y) < 3.0f && du > 0.0f && du < 192.0f) {
            const int p = atomicAdd(&s_cnt, 1);
            if (p < CAP) {
                s_idx[p] = g_bin_idx[(size_t)b * KM + j];
                s_du[p]  = du;
            }
        }
    }
    s_q[tid] = g_Q[(size_t)row * KC + tid];
    __syncthreads();

    const int cnt = min(s_cnt, CAP);
    float* attn_row = attn + (size_t)row * KM;
    float4* attn_row4 = reinterpret_cast<float4*>(attn_row);

    if (cnt > 0) {
        // scores: one warp per valid entry, float4 dot
        const int wid = tid >> 5, lane = tid & 31;
        const float* Kb = g_K + (size_t)b * KM * KC;
        const float4* q4 = reinterpret_cast<const float4*>(s_q);
        for (int i = wid; i < cnt; i += 8) {
            const float4* k4 = reinterpret_cast<const float4*>(
                Kb + (size_t)s_idx[i] * KC);
            float4 qa = q4[lane],      ka = __ldg(k4 + lane);
            float4 qb = q4[lane + 32], kb = __ldg(k4 + lane + 32);
            float sum = qa.x * ka.x + qa.y * ka.y + qa.z * ka.z + qa.w * ka.w
                      + qb.x * kb.x + qb.y * kb.y + qb.z * kb.z + qb.w * kb.w;
#pragma unroll
            for (int o = 16; o > 0; o >>= 1)
                sum += __shfl_xor_sync(0xffffffffu, sum, o);
            if (lane == 0) s_sc[i] = sum * 0.0625f;   // 1/sqrt(256)
        }
        __syncthreads();

        // max
        float mx = -1e30f;
        for (int i = tid; i < cnt; i += 256) mx = fmaxf(mx, s_sc[i]);
        s_red[tid] = mx; __syncthreads();
        for (int s = 128; s > 0; s >>= 1) {
            if (tid < s) s_red[tid] = fmaxf(s_red[tid], s_red[tid + s]);
            __syncthreads();
        }
        mx = s_red[0];
        __syncthreads();

        // sum exp
        float sm = 0.0f;
        for (int i = tid; i < cnt; i += 256) {
            const float e = expf(s_sc[i] - mx);
            s_sc[i] = e;
            sm += e;
        }
        s_red[tid] = sm; __syncthreads();
        for (int s = 128; s > 0; s >>= 1) {
            if (tid < s) s_red[tid] += s_red[tid + s];
            __syncthreads();
        }
        const float inv = 1.0f / s_red[0];
        __syncthreads();

        // weights + disparity
        float dsum = 0.0f;
        for (int i = tid; i < cnt; i += 256) {
            const float w = s_sc[i] * inv;
            s_sc[i] = w;
            dsum += w * s_du[i];
        }
        s_red[tid] = dsum; __syncthreads();
        for (int s = 128; s > 0; s >>= 1) {
            if (tid < s) s_red[tid] += s_red[tid + s];
            __syncthreads();
        }

        // attn row: vector zero-fill + scatter
        const float4 z4 = make_float4(0.f, 0.f, 0.f, 0.f);
        for (int m = tid; m < KM / 4; m += 256) attn_row4[m] = z4;
        __syncthreads();
        for (int i = tid; i < cnt; i += 256) attn_row[s_idx[i]] = s_sc[i];

        // matched features
        const float* Vb = g_V + (size_t)b * KM * KC;
        float a = 0.0f;
        for (int i = 0; i < cnt; i++)
            a = fmaf(s_sc[i], __ldg(Vb + (size_t)s_idx[i] * KC + tid), a);
        g_MF[(size_t)row * KC + tid] = a;

        if (tid == 0) { disp[row] = s_red[0]; conf[row] = 1.0f; }
    } else {
        // fully-masked row: uniform 1/M softmax (exact)
        const float wu = 1.0f / (float)KM;
        const float4 w4 = make_float4(wu, wu, wu, wu);
        for (int m = tid; m < KM / 4; m += 256) attn_row4[m] = w4;

        const float* Vb = g_V + (size_t)b * KM * KC;
        float a = 0.0f;
        for (int m = 0; m < KM; m++) a += Vb[(size_t)m * KC + tid];
        g_MF[(size_t)row * KC + tid] = a * wu;

        const float* kR = kptsR + (size_t)b * KM * 2;
        float su = 0.0f;
        for (int m = tid; m < KM; m += 256) su += kR[2 * m];
        s_red[tid] = su; __syncthreads();
        for (int s = 128; s > 0; s >>= 1) {
            if (tid < s) s_red[tid] += s_red[tid + s];
            __syncthreads();
        }
        if (tid == 0) { disp[row] = uL - s_red[0] * wu; conf[row] = 0.0f; }
    }
}

// ---------------------------------------------------------------------------
extern "C" void kernel_launch(void* const* d_in, const int* in_sizes, int n_in,
                              void* d_out, int out_size)
{
    (void)in_sizes; (void)n_in; (void)out_size;

    const float* nodes_L = (const float*)d_in[0];
    const float* nodes_R = (const float*)d_in[1];
    const float* kpts_L  = (const float*)d_in[2];
    const float* kpts_R  = (const float*)d_in[3];
    const float* Wq = (const float*)d_in[4];
    const float* bq = (const float*)d_in[5];
    const float* Wk = (const float*)d_in[6];
    const float* bk = (const float*)d_in[7];
    const float* Wv = (const float*)d_in[8];
    const float* bv = (const float*)d_in[9];
    const float* Wm = (const float*)d_in[10];
    const float* bm = (const float*)d_in[11];

    float* out      = (float*)d_out;
    float* out_feat = out;
    float* out_disp = out_feat + (size_t)KB * KN * KC;
    float* out_conf = out_disp + (size_t)KB * KN;
    float* out_attn = out_conf + (size_t)KB * KN;

    float *pQ, *pK, *pV, *pMF;
    cudaGetSymbolAddress((void**)&pQ,  g_Q);
    cudaGetSymbolAddress((void**)&pK,  g_K);
    cudaGetSymbolAddress((void**)&pV,  g_V);
    cudaGetSymbolAddress((void**)&pMF, g_MF);

    build_bins_kernel<<<KB, 512>>>(kpts_R);

    dim3 qkv_grid(KC / BN, KROWS / BM, 3);   // (2, 128, 3)
    gemm_qkv<<<qkv_grid, 256>>>(nodes_L, nodes_R, Wq, bq, Wk, bk, Wv, bv,
                                pQ, pK, pV);

    attn_sparse_kernel<<<KB * KN, 256>>>(kpts_L, kpts_R,
                                         out_attn, out_disp, out_conf);

    dim3 out_grid(KC / BN, KROWS / BM);
    gemm_out<<<out_grid, 256>>>(pMF, Wm, bm, out_feat);
}